// round 1
// baseline (speedup 1.0000x reference)
#include <cuda_runtime.h>
#include <cuda_bf16.h>
#include <cstdint>

// Problem constants
#define N_ROWS 16384          // 16*32*32
#define N_CODES 8192
#define DIM 64

#define BM 128                // rows per block
#define BN 128                // codebook cols per chunk
#define TM 8                  // rows per thread
#define TN 8                  // cols per thread
#define XS_STRIDE 66          // padded float stride (conflict-free LDS.64)

// Scratch (device globals: no allocation allowed)
__device__ int   g_idx[N_ROWS];
__device__ float g_cnorm[N_CODES];

// ---------------------------------------------------------------------------
// Kernel A: codebook squared norms
// ---------------------------------------------------------------------------
__global__ void cnorm_kernel(const float* __restrict__ cb) {
    int k = blockIdx.x * blockDim.x + threadIdx.x;
    const float4* p = reinterpret_cast<const float4*>(cb + (size_t)k * DIM);
    float s = 0.f;
#pragma unroll
    for (int j = 0; j < DIM / 4; j++) {
        float4 v = p[j];
        s += v.x * v.x + v.y * v.y + v.z * v.z + v.w * v.w;
    }
    g_cnorm[k] = s;
}

// ---------------------------------------------------------------------------
// Kernel B: fused distance GEMM + argmin.
// dist(n,k) = ||c_k||^2 - 2 * <x_n, c_k>   (same ordering as reference,
// constant ||x||^2 dropped). Inner product via packed fma.rn.f32x2 over
// d-pairs: 2 MACs per FFMA2 instruction.
// ---------------------------------------------------------------------------
__device__ __forceinline__ unsigned long long ull_min(unsigned long long a,
                                                      unsigned long long b) {
    return a < b ? a : b;
}

__global__ void __launch_bounds__(256, 1)
argmin_kernel(const float* __restrict__ x, const float* __restrict__ cb) {
    extern __shared__ float sm[];
    float* xs  = sm;                                 // [BM][XS_STRIDE]
    float* cs  = sm + BM * XS_STRIDE;                // [BN][XS_STRIDE]
    float* cns = sm + 2 * BM * XS_STRIDE;            // [BN]

    const int tid = threadIdx.x;
    const int tx  = tid & 15;    // 0..15 -> col group
    const int ty  = tid >> 4;    // 0..15 -> row group
    const int row0 = blockIdx.x * BM;

    // Load x tile once: BM x 64 floats (float4 from gmem, scalar to padded smem)
    for (int t = tid; t < BM * (DIM / 4); t += 256) {
        int r = t >> 4, c4 = t & 15;
        float4 v = reinterpret_cast<const float4*>(x + (size_t)(row0 + r) * DIM)[c4];
        float* dst = xs + r * XS_STRIDE + c4 * 4;
        dst[0] = v.x; dst[1] = v.y; dst[2] = v.z; dst[3] = v.w;
    }

    unsigned long long best[TM];
#pragma unroll
    for (int i = 0; i < TM; i++) best[i] = ~0ULL;

    unsigned long long acc[TM][TN];

    for (int chunk = 0; chunk < N_CODES / BN; chunk++) {
        __syncthreads();   // protects xs (1st iter) and cs (later iters)
        // Load codebook chunk: BN x 64 floats
        const float* cbase = cb + (size_t)chunk * BN * DIM;
        for (int t = tid; t < BN * (DIM / 4); t += 256) {
            int r = t >> 4, c4 = t & 15;
            float4 v = reinterpret_cast<const float4*>(cbase + (size_t)r * DIM)[c4];
            float* dst = cs + r * XS_STRIDE + c4 * 4;
            dst[0] = v.x; dst[1] = v.y; dst[2] = v.z; dst[3] = v.w;
        }
        if (tid < BN) cns[tid] = g_cnorm[chunk * BN + tid];
        __syncthreads();

#pragma unroll
        for (int i = 0; i < TM; i++)
#pragma unroll
            for (int j = 0; j < TN; j++) acc[i][j] = 0ULL;

        // Main loop over 32 d-pairs
#pragma unroll 8
        for (int dp = 0; dp < DIM / 2; dp++) {
            unsigned long long ra[TM], rb[TN];
#pragma unroll
            for (int i = 0; i < TM; i++)
                ra[i] = *reinterpret_cast<const unsigned long long*>(
                    xs + (ty * TM + i) * XS_STRIDE + dp * 2);
#pragma unroll
            for (int j = 0; j < TN; j++)
                rb[j] = *reinterpret_cast<const unsigned long long*>(
                    cs + (tx + 16 * j) * XS_STRIDE + dp * 2);
#pragma unroll
            for (int i = 0; i < TM; i++)
#pragma unroll
                for (int j = 0; j < TN; j++)
                    asm volatile("fma.rn.f32x2 %0, %1, %2, %0;"
                                 : "+l"(acc[i][j])
                                 : "l"(ra[i]), "l"(rb[j]));
        }

        // Epilogue: fold pair-halves, form distance, update packed argmin
#pragma unroll
        for (int j = 0; j < TN; j++) {
            unsigned kcol = (unsigned)(chunk * BN + tx + 16 * j);
            float cn = cns[tx + 16 * j];
#pragma unroll
            for (int i = 0; i < TM; i++) {
                unsigned lo, hi;
                asm("mov.b64 {%0, %1}, %2;" : "=r"(lo), "=r"(hi) : "l"(acc[i][j]));
                float dot = __uint_as_float(lo) + __uint_as_float(hi);
                float dist = fmaf(-2.0f, dot, cn);
                unsigned u = __float_as_uint(dist);
                u = (u & 0x80000000u) ? ~u : (u | 0x80000000u);
                unsigned long long key = ((unsigned long long)u << 32) | kcol;
                best[i] = ull_min(best[i], key);
            }
        }
    }

    // Reduce across the 16 tx lanes that share each row (within half-warp)
#pragma unroll
    for (int i = 0; i < TM; i++) {
        unsigned long long b = best[i];
#pragma unroll
        for (int off = 8; off >= 1; off >>= 1) {
            unsigned long long o = __shfl_xor_sync(0xffffffffu, b, off);
            b = ull_min(b, o);
        }
        if (tx == 0) g_idx[row0 + ty * TM + i] = (int)(b & 0xffffffffu);
    }
}

// ---------------------------------------------------------------------------
// Kernel C1: one-hot (streams 512 MiB of float4 stores)
// ---------------------------------------------------------------------------
__global__ void onehot_kernel(float* __restrict__ out) {
    unsigned i = blockIdx.x * 256u + threadIdx.x;   // float4 index
    unsigned n = i >> 11;                            // 2048 float4 per row
    unsigned q = i & 2047u;
    int k = __ldg(&g_idx[n]);
    float4 v = make_float4(0.f, 0.f, 0.f, 0.f);
    if ((unsigned)(k >> 2) == q) {
        reinterpret_cast<float*>(&v)[k & 3] = 1.0f;
    }
    reinterpret_cast<float4*>(out)[i] = v;
}

// ---------------------------------------------------------------------------
// Kernel C2: quantized = gather codebook rows
// ---------------------------------------------------------------------------
__global__ void gather_kernel(const float* __restrict__ cb,
                              float* __restrict__ outq) {
    unsigned i = blockIdx.x * 256u + threadIdx.x;   // float4 index, N_ROWS*16 total
    unsigned n = i >> 4;
    unsigned c4 = i & 15u;
    int k = __ldg(&g_idx[n]);
    reinterpret_cast<float4*>(outq)[i] =
        reinterpret_cast<const float4*>(cb + (size_t)k * DIM)[c4];
}

// ---------------------------------------------------------------------------
extern "C" void kernel_launch(void* const* d_in, const int* in_sizes, int n_in,
                              void* d_out, int out_size) {
    const float* x  = (const float*)d_in[0];
    const float* cb = (const float*)d_in[1];
    float* out      = (float*)d_out;
    float* out_disc = out;                                  // [N_ROWS, N_CODES]
    float* out_q    = out + (size_t)N_ROWS * N_CODES;       // [N_ROWS, DIM]

    const int smem = (2 * BM * XS_STRIDE + BN) * sizeof(float);  // 68096 B
    cudaFuncSetAttribute(argmin_kernel,
                         cudaFuncAttributeMaxDynamicSharedMemorySize, smem);

    cnorm_kernel<<<N_CODES / 256, 256>>>(cb);
    argmin_kernel<<<N_ROWS / BM, 256, smem>>>(x, cb);
    onehot_kernel<<<(N_ROWS * (N_CODES / 4)) / 256, 256>>>(out_disc);
    gather_kernel<<<(N_ROWS * (DIM / 4)) / 256, 256>>>(cb, out_q);
}

// round 5
// speedup vs baseline: 2.1012x; 2.1012x over previous
#include <cuda_runtime.h>
#include <cuda_fp16.h>
#include <cstdint>

#define N_ROWS   16384
#define N_CODES  8192
#define DIM      64
#define BM       128
#define BN       32
#define NCHUNK   (N_CODES / BN)      // 256
#define KEXT     192                  // [xh(64) | xl(64) | xh(64)]
#define THREADS  256
#define ROWB     400                  // padded SMEM row bytes (25*16; 25 mod 8 = 1 -> no LDSM conflicts)
#define BBUF     (BN * ROWB)          // 12800 B per B stage

// device scratch
__device__ __align__(16) __half g_cbe[(size_t)N_CODES * KEXT];  // [ch|ch|cl] per code
__device__ __align__(16) float  g_cnorm[N_CODES];
__device__ int g_idx[N_ROWS];

// ---------------- helpers ----------------
__device__ __forceinline__ uint32_t h2_as_u32(__half2 h) {
    uint32_t u;
    __builtin_memcpy(&u, &h, 4);
    return u;
}
__device__ __forceinline__ uint32_t pack_h2(__half a, __half b) {
    return h2_as_u32(__halves2half2(a, b));
}
__device__ __forceinline__ uint32_t smem_u32(const void* p) {
    uint32_t a;
    asm("{ .reg .u64 t; cvta.to.shared.u64 t, %1; cvt.u32.u64 %0, t; }" : "=r"(a) : "l"(p));
    return a;
}
#define CPA16(d,s)   asm volatile("cp.async.cg.shared.global [%0], [%1], 16;" :: "r"(d), "l"(s) : "memory")
#define CPA_COMMIT() asm volatile("cp.async.commit_group;" ::: "memory")
#define CPA_WAIT0()  asm volatile("cp.async.wait_group 0;" ::: "memory")

// non-trans ldmatrix: correct distribution for both A (row-major rows) and
// B (code-major rows: lane gets 2 consecutive k of one code) of mma.row.col
#define LDM_X4(r0,r1,r2,r3,a) \
    asm volatile("ldmatrix.sync.aligned.m8n8.x4.shared.b16 {%0,%1,%2,%3}, [%4];" \
                 : "=r"(r0), "=r"(r1), "=r"(r2), "=r"(r3) : "r"(a))

__device__ __forceinline__ void mma16816(float* d, const uint32_t* a,
                                         uint32_t b0, uint32_t b1) {
    asm volatile("mma.sync.aligned.m16n8k16.row.col.f32.f16.f16.f32 "
                 "{%0,%1,%2,%3}, {%4,%5,%6,%7}, {%8,%9}, {%0,%1,%2,%3};"
                 : "+f"(d[0]), "+f"(d[1]), "+f"(d[2]), "+f"(d[3])
                 : "r"(a[0]), "r"(a[1]), "r"(a[2]), "r"(a[3]), "r"(b0), "r"(b1));
}

// ---------------------------------------------------------------------------
// Prep: codebook -> fp16 [ch|ch|cl] + squared norms. One warp per code.
// ---------------------------------------------------------------------------
__global__ void prep_kernel(const float* __restrict__ cb) {
    int g = blockIdx.x * blockDim.x + threadIdx.x;
    int code = g >> 5, lane = g & 31;
    float2 v = reinterpret_cast<const float2*>(cb + (size_t)code * DIM)[lane];
    __half hx = __float2half_rn(v.x), hy = __float2half_rn(v.y);
    float lx = v.x - __half2float(hx), ly = v.y - __half2float(hy);
    __half2 hh = __halves2half2(hx, hy);
    __half2 ll = __halves2half2(__float2half_rn(lx), __float2half_rn(ly));
    __half2* dst = reinterpret_cast<__half2*>(g_cbe + (size_t)code * KEXT);
    dst[lane] = hh;          // seg0: ch
    dst[32 + lane] = hh;     // seg1: ch (paired with xl)
    dst[64 + lane] = ll;     // seg2: cl (paired with xh)
    float s = v.x * v.x + v.y * v.y;
#pragma unroll
    for (int o = 16; o; o >>= 1) s += __shfl_xor_sync(~0u, s, o);
    if (lane == 0) g_cnorm[code] = s;
}

// ---------------------------------------------------------------------------
// Fused mma.sync distance GEMM + argmin.
// 8 warps x m16; A_ext held in registers; B double-buffered via cp.async.
// ---------------------------------------------------------------------------
__global__ void __launch_bounds__(THREADS, 1)
argmin_mma(const float* __restrict__ x) {
    extern __shared__ char smem[];
    // layout: A staging [128][400] then B ring [2][12800]
    const uint32_t As = smem_u32(smem);
    const uint32_t Bs = As + BM * ROWB;

    const int tid = threadIdx.x, wid = tid >> 5, lane = tid & 31;
    const int row0 = blockIdx.x * BM;

    // ---- Build A_ext staging: row = [xh(128B) | xl(128B) | xh(128B)] ----
    for (int t = tid; t < BM * (DIM / 4); t += THREADS) {
        int row = t >> 4, q = t & 15;                    // q = float4 within row
        float4 v = reinterpret_cast<const float4*>(x)[(size_t)(row0 + row) * 16 + q];
        __half h0 = __float2half_rn(v.x), h1 = __float2half_rn(v.y);
        __half h2 = __float2half_rn(v.z), h3 = __float2half_rn(v.w);
        uint32_t hp0 = pack_h2(h0, h1);
        uint32_t hp1 = pack_h2(h2, h3);
        uint32_t lp0 = pack_h2(__float2half_rn(v.x - __half2float(h0)),
                               __float2half_rn(v.y - __half2float(h1)));
        uint32_t lp1 = pack_h2(__float2half_rn(v.z - __half2float(h2)),
                               __float2half_rn(v.w - __half2float(h3)));
        uint32_t base = As + row * ROWB + q * 8;
        asm volatile("st.shared.v2.b32 [%0], {%1,%2};" :: "r"(base), "r"(hp0), "r"(hp1));
        asm volatile("st.shared.v2.b32 [%0], {%1,%2};" :: "r"(base + 256), "r"(hp0), "r"(hp1));
        asm volatile("st.shared.v2.b32 [%0], {%1,%2};" :: "r"(base + 128), "r"(lp0), "r"(lp1));
    }
    __syncthreads();

    // ---- Load persistent A fragments: 12 kgroups x 4 regs ----
    uint32_t afr[12][4];
    {
        int t = lane >> 3;
        int arow = wid * 16 + ((t & 1) << 3) + (lane & 7);
        uint32_t abase = As + arow * ROWB + ((t >> 1) << 4);
#pragma unroll
        for (int kg = 0; kg < 12; kg++)
            LDM_X4(afr[kg][0], afr[kg][1], afr[kg][2], afr[kg][3], abase + kg * 32);
    }
    __syncthreads();   // A staging dead; B ring lives at its own region anyway

    // per-lane ldmatrix B address: lanes 0-7 -> codes 0-7 (k0-7),
    // 8-15 -> codes 0-7 (k8-15), 16-23 -> codes 8-15 (k0-7), 24-31 -> codes 8-15 (k8-15)
    const uint32_t bl0 = Bs + ((lane >> 4) * 8 + (lane & 7)) * ROWB + ((lane >> 3) & 1) * 16;

    // ---- prefetch chunk 0 ----
    {
#pragma unroll
        for (int j = 0; j < 3; j++) {
            int i = tid + j * THREADS;           // 16B op index (768 total)
            int code = i / 24, off = (i % 24) * 16;
            CPA16(Bs + code * ROWB + off,
                  (const char*)g_cbe + (size_t)0 + i * 16);
        }
        CPA_COMMIT();
    }

    float best0 = 3.4e38f, best1 = 3.4e38f;
    int idx0 = 0, idx1 = 0;

    for (int c = 0; c < NCHUNK; c++) {
        CPA_WAIT0();
        __syncthreads();
        if (c + 1 < NCHUNK) {
            const char* src = (const char*)g_cbe + (size_t)(c + 1) * BN * KEXT * 2;
            uint32_t dbuf = Bs + ((c + 1) & 1) * BBUF;
#pragma unroll
            for (int j = 0; j < 3; j++) {
                int i = tid + j * THREADS;
                int code = i / 24, off = (i % 24) * 16;
                CPA16(dbuf + code * ROWB + off, src + i * 16);
            }
            CPA_COMMIT();
        }

        const uint32_t bb = bl0 + (c & 1) * BBUF;
        float acc[4][4];
#pragma unroll
        for (int f = 0; f < 4; f++)
#pragma unroll
            for (int j = 0; j < 4; j++) acc[f][j] = 0.f;

#pragma unroll
        for (int kg = 0; kg < 12; kg++) {
            uint32_t b[8];
            LDM_X4(b[0], b[1], b[2], b[3], bb + kg * 32);
            LDM_X4(b[4], b[5], b[6], b[7], bb + kg * 32 + 16 * ROWB);
            mma16816(acc[0], afr[kg], b[0], b[1]);
            mma16816(acc[1], afr[kg], b[2], b[3]);
            mma16816(acc[2], afr[kg], b[4], b[5]);
            mma16816(acc[3], afr[kg], b[6], b[7]);
        }

        // epilogue: dist = ||c||^2 - 2*dot ; strict < keeps lowest index
        int base = c * BN + ((lane & 3) << 1);
#pragma unroll
        for (int f = 0; f < 4; f++) {
            int col = base + f * 8;
            float cn0 = __ldg(&g_cnorm[col]);
            float cn1 = __ldg(&g_cnorm[col + 1]);
            float d0 = fmaf(-2.f, acc[f][0], cn0);
            float d1 = fmaf(-2.f, acc[f][1], cn1);
            float d2 = fmaf(-2.f, acc[f][2], cn0);
            float d3 = fmaf(-2.f, acc[f][3], cn1);
            if (d0 < best0) { best0 = d0; idx0 = col; }
            if (d1 < best0) { best0 = d1; idx0 = col + 1; }
            if (d2 < best1) { best1 = d2; idx1 = col; }
            if (d3 < best1) { best1 = d3; idx1 = col + 1; }
        }
    }

    // reduce across the 4 lanes sharing each row; tie -> lowest index
#pragma unroll
    for (int off = 1; off <= 2; off <<= 1) {
        float ob = __shfl_xor_sync(~0u, best0, off);
        int   oi = __shfl_xor_sync(~0u, idx0, off);
        if (ob < best0 || (ob == best0 && oi < idx0)) { best0 = ob; idx0 = oi; }
        ob = __shfl_xor_sync(~0u, best1, off);
        oi = __shfl_xor_sync(~0u, idx1, off);
        if (ob < best1 || (ob == best1 && oi < idx1)) { best1 = ob; idx1 = oi; }
    }
    if ((lane & 3) == 0) {
        int r = row0 + wid * 16 + (lane >> 2);
        g_idx[r] = idx0;
        g_idx[r + 8] = idx1;
    }
}

// ---------------------------------------------------------------------------
// One-hot: 512 MiB streaming stores.
// ---------------------------------------------------------------------------
__global__ void onehot_kernel(float* __restrict__ out) {
    unsigned i = blockIdx.x * 256u + threadIdx.x;   // float4 index
    unsigned n = i >> 11;                            // 2048 float4 per row
    unsigned q = i & 2047u;
    int k = __ldg(&g_idx[n]);
    float4 v = make_float4(0.f, 0.f, 0.f, 0.f);
    if ((unsigned)(k >> 2) == q) reinterpret_cast<float*>(&v)[k & 3] = 1.0f;
    __stcs(reinterpret_cast<float4*>(out) + i, v);
}

__global__ void gather_kernel(const float* __restrict__ cb, float* __restrict__ outq) {
    unsigned i = blockIdx.x * 256u + threadIdx.x;
    unsigned n = i >> 4;
    unsigned c4 = i & 15u;
    int k = __ldg(&g_idx[n]);
    reinterpret_cast<float4*>(outq)[i] =
        reinterpret_cast<const float4*>(cb + (size_t)k * DIM)[c4];
}

// ---------------------------------------------------------------------------
extern "C" void kernel_launch(void* const* d_in, const int* in_sizes, int n_in,
                              void* d_out, int out_size) {
    const float* x  = (const float*)d_in[0];
    const float* cb = (const float*)d_in[1];
    float* out      = (float*)d_out;
    float* out_disc = out;
    float* out_q    = out + (size_t)N_ROWS * N_CODES;

    const int smem = BM * ROWB + 2 * BBUF;   // 51200 + 25600 = 76800
    cudaFuncSetAttribute(argmin_mma, cudaFuncAttributeMaxDynamicSharedMemorySize, smem);

    prep_kernel<<<(N_CODES * 32) / 256, 256>>>(cb);
    argmin_mma<<<N_ROWS / BM, THREADS, smem>>>(x);
    onehot_kernel<<<(N_ROWS * (N_CODES / 4)) / 256, 256>>>(out_disc);
    gather_kernel<<<(N_ROWS * (DIM / 4)) / 256, 256>>>(cb, out_q);
}

// round 6
// speedup vs baseline: 2.3095x; 1.0991x over previous
#include <cuda_runtime.h>
#include <cuda_fp16.h>
#include <cstdint>

#define N_ROWS   16384
#define N_CODES  8192
#define DIM      64
#define BM       128
#define BN       32
#define NCHUNK   (N_CODES / BN)      // 256
#define KEXT     192                  // [xh(64) | xl(64) | xh(64)]
#define THREADS  256
#define ROWB     400                  // padded SMEM row bytes
#define BBUF     (BN * ROWB)          // 12800 B per B stage
#define NARG     (N_ROWS / BM)        // 128 argmin CTAs
#define NZERO    128                  // zerofill CTAs
#define DISC_F4  ((size_t)N_ROWS * N_CODES / 4)   // 33554432 float4

// device scratch
__device__ __align__(16) __half g_cbe[(size_t)N_CODES * KEXT];  // [ch|ch|cl] per code
__device__ __align__(16) float  g_cnorm[N_CODES];
__device__ int g_idx[N_ROWS];

// ---------------- helpers ----------------
__device__ __forceinline__ uint32_t h2_as_u32(__half2 h) {
    uint32_t u;
    __builtin_memcpy(&u, &h, 4);
    return u;
}
__device__ __forceinline__ uint32_t pack_h2(__half a, __half b) {
    return h2_as_u32(__halves2half2(a, b));
}
__device__ __forceinline__ uint32_t smem_u32(const void* p) {
    uint32_t a;
    asm("{ .reg .u64 t; cvta.to.shared.u64 t, %1; cvt.u32.u64 %0, t; }" : "=r"(a) : "l"(p));
    return a;
}
#define CPA16(d,s)   asm volatile("cp.async.cg.shared.global [%0], [%1], 16;" :: "r"(d), "l"(s) : "memory")
#define CPA_COMMIT() asm volatile("cp.async.commit_group;" ::: "memory")
#define CPA_WAIT0()  asm volatile("cp.async.wait_group 0;" ::: "memory")

#define LDM_X4(r0,r1,r2,r3,a) \
    asm volatile("ldmatrix.sync.aligned.m8n8.x4.shared.b16 {%0,%1,%2,%3}, [%4];" \
                 : "=r"(r0), "=r"(r1), "=r"(r2), "=r"(r3) : "r"(a))

__device__ __forceinline__ void mma16816(float* d, const uint32_t* a,
                                         uint32_t b0, uint32_t b1) {
    asm volatile("mma.sync.aligned.m16n8k16.row.col.f32.f16.f16.f32 "
                 "{%0,%1,%2,%3}, {%4,%5,%6,%7}, {%8,%9}, {%0,%1,%2,%3};"
                 : "+f"(d[0]), "+f"(d[1]), "+f"(d[2]), "+f"(d[3])
                 : "r"(a[0]), "r"(a[1]), "r"(a[2]), "r"(a[3]), "r"(b0), "r"(b1));
}

// ---------------------------------------------------------------------------
// Prep: codebook -> fp16 [ch|ch|cl] + squared norms. One warp per code.
// ---------------------------------------------------------------------------
__global__ void prep_kernel(const float* __restrict__ cb) {
    int g = blockIdx.x * blockDim.x + threadIdx.x;
    int code = g >> 5, lane = g & 31;
    float2 v = reinterpret_cast<const float2*>(cb + (size_t)code * DIM)[lane];
    __half hx = __float2half_rn(v.x), hy = __float2half_rn(v.y);
    float lx = v.x - __half2float(hx), ly = v.y - __half2float(hy);
    __half2 hh = __halves2half2(hx, hy);
    __half2 ll = __halves2half2(__float2half_rn(lx), __float2half_rn(ly));
    __half2* dst = reinterpret_cast<__half2*>(g_cbe + (size_t)code * KEXT);
    dst[lane] = hh;
    dst[32 + lane] = hh;
    dst[64 + lane] = ll;
    float s = v.x * v.x + v.y * v.y;
#pragma unroll
    for (int o = 16; o; o >>= 1) s += __shfl_xor_sync(~0u, s, o);
    if (lane == 0) g_cnorm[code] = s;
}

// ---------------------------------------------------------------------------
// Fused: bid < NARG -> mma.sync distance GEMM + argmin (unchanged from R5);
//        bid >= NARG -> stream zeros into the one-hot output concurrently.
// ---------------------------------------------------------------------------
__global__ void __launch_bounds__(THREADS, 1)
argmin_fused(const float* __restrict__ x, float* __restrict__ out_disc) {
    const int tid = threadIdx.x;

    if (blockIdx.x >= NARG) {
        // ---- zerofill CTA: pure streaming stores, overlaps argmin compute ----
        size_t i = (size_t)(blockIdx.x - NARG) * THREADS + tid;
        const size_t stride = (size_t)NZERO * THREADS;   // 32768
        float4 z = make_float4(0.f, 0.f, 0.f, 0.f);
        float4* o = reinterpret_cast<float4*>(out_disc);
#pragma unroll 4
        for (; i < DISC_F4; i += stride) __stcs(o + i, z);
        return;
    }

    extern __shared__ char smem[];
    const uint32_t As = smem_u32(smem);
    const uint32_t Bs = As + BM * ROWB;

    const int wid = tid >> 5, lane = tid & 31;
    const int row0 = blockIdx.x * BM;

    // ---- Build A_ext staging: row = [xh(128B) | xl(128B) | xh(128B)] ----
    for (int t = tid; t < BM * (DIM / 4); t += THREADS) {
        int row = t >> 4, q = t & 15;
        float4 v = reinterpret_cast<const float4*>(x)[(size_t)(row0 + row) * 16 + q];
        __half h0 = __float2half_rn(v.x), h1 = __float2half_rn(v.y);
        __half h2 = __float2half_rn(v.z), h3 = __float2half_rn(v.w);
        uint32_t hp0 = pack_h2(h0, h1);
        uint32_t hp1 = pack_h2(h2, h3);
        uint32_t lp0 = pack_h2(__float2half_rn(v.x - __half2float(h0)),
                               __float2half_rn(v.y - __half2float(h1)));
        uint32_t lp1 = pack_h2(__float2half_rn(v.z - __half2float(h2)),
                               __float2half_rn(v.w - __half2float(h3)));
        uint32_t base = As + row * ROWB + q * 8;
        asm volatile("st.shared.v2.b32 [%0], {%1,%2};" :: "r"(base), "r"(hp0), "r"(hp1));
        asm volatile("st.shared.v2.b32 [%0], {%1,%2};" :: "r"(base + 256), "r"(hp0), "r"(hp1));
        asm volatile("st.shared.v2.b32 [%0], {%1,%2};" :: "r"(base + 128), "r"(lp0), "r"(lp1));
    }
    __syncthreads();

    // ---- Persistent A fragments ----
    uint32_t afr[12][4];
    {
        int t = lane >> 3;
        int arow = wid * 16 + ((t & 1) << 3) + (lane & 7);
        uint32_t abase = As + arow * ROWB + ((t >> 1) << 4);
#pragma unroll
        for (int kg = 0; kg < 12; kg++)
            LDM_X4(afr[kg][0], afr[kg][1], afr[kg][2], afr[kg][3], abase + kg * 32);
    }
    __syncthreads();

    const uint32_t bl0 = Bs + ((lane >> 4) * 8 + (lane & 7)) * ROWB + ((lane >> 3) & 1) * 16;

    // ---- prefetch chunk 0 ----
    {
#pragma unroll
        for (int j = 0; j < 3; j++) {
            int i = tid + j * THREADS;
            int code = i / 24, off = (i % 24) * 16;
            CPA16(Bs + code * ROWB + off, (const char*)g_cbe + (size_t)0 + i * 16);
        }
        CPA_COMMIT();
    }

    float best0 = 3.4e38f, best1 = 3.4e38f;
    int idx0 = 0, idx1 = 0;

    for (int c = 0; c < NCHUNK; c++) {
        CPA_WAIT0();
        __syncthreads();
        if (c + 1 < NCHUNK) {
            const char* src = (const char*)g_cbe + (size_t)(c + 1) * BN * KEXT * 2;
            uint32_t dbuf = Bs + ((c + 1) & 1) * BBUF;
#pragma unroll
            for (int j = 0; j < 3; j++) {
                int i = tid + j * THREADS;
                int code = i / 24, off = (i % 24) * 16;
                CPA16(dbuf + code * ROWB + off, src + i * 16);
            }
            CPA_COMMIT();
        }

        const uint32_t bb = bl0 + (c & 1) * BBUF;
        float acc[4][4];
#pragma unroll
        for (int f = 0; f < 4; f++)
#pragma unroll
            for (int j = 0; j < 4; j++) acc[f][j] = 0.f;

#pragma unroll
        for (int kg = 0; kg < 12; kg++) {
            uint32_t b[8];
            LDM_X4(b[0], b[1], b[2], b[3], bb + kg * 32);
            LDM_X4(b[4], b[5], b[6], b[7], bb + kg * 32 + 16 * ROWB);
            mma16816(acc[0], afr[kg], b[0], b[1]);
            mma16816(acc[1], afr[kg], b[2], b[3]);
            mma16816(acc[2], afr[kg], b[4], b[5]);
            mma16816(acc[3], afr[kg], b[6], b[7]);
        }

        int base = c * BN + ((lane & 3) << 1);
#pragma unroll
        for (int f = 0; f < 4; f++) {
            int col = base + f * 8;
            float cn0 = __ldg(&g_cnorm[col]);
            float cn1 = __ldg(&g_cnorm[col + 1]);
            float d0 = fmaf(-2.f, acc[f][0], cn0);
            float d1 = fmaf(-2.f, acc[f][1], cn1);
            float d2 = fmaf(-2.f, acc[f][2], cn0);
            float d3 = fmaf(-2.f, acc[f][3], cn1);
            if (d0 < best0) { best0 = d0; idx0 = col; }
            if (d1 < best0) { best0 = d1; idx0 = col + 1; }
            if (d2 < best1) { best1 = d2; idx1 = col; }
            if (d3 < best1) { best1 = d3; idx1 = col + 1; }
        }
    }

#pragma unroll
    for (int off = 1; off <= 2; off <<= 1) {
        float ob = __shfl_xor_sync(~0u, best0, off);
        int   oi = __shfl_xor_sync(~0u, idx0, off);
        if (ob < best0 || (ob == best0 && oi < idx0)) { best0 = ob; idx0 = oi; }
        ob = __shfl_xor_sync(~0u, best1, off);
        oi = __shfl_xor_sync(~0u, idx1, off);
        if (ob < best1 || (ob == best1 && oi < idx1)) { best1 = ob; idx1 = oi; }
    }
    if ((lane & 3) == 0) {
        int r = row0 + wid * 16 + (lane >> 2);
        g_idx[r] = idx0;
        g_idx[r + 8] = idx1;
    }
}

// ---------------------------------------------------------------------------
// Finalize: gather quantized rows + scatter the 1.0s into the one-hot.
// ---------------------------------------------------------------------------
__global__ void finalize_kernel(const float* __restrict__ cb,
                                float* __restrict__ out_disc,
                                float* __restrict__ outq) {
    unsigned i = blockIdx.x * 256u + threadIdx.x;   // float4 index, N_ROWS*16 total
    unsigned n = i >> 4;
    unsigned c4 = i & 15u;
    int k = __ldg(&g_idx[n]);
    reinterpret_cast<float4*>(outq)[i] =
        reinterpret_cast<const float4*>(cb + (size_t)k * DIM)[c4];
    if (c4 == 0) out_disc[(size_t)n * N_CODES + k] = 1.0f;
}

// ---------------------------------------------------------------------------
extern "C" void kernel_launch(void* const* d_in, const int* in_sizes, int n_in,
                              void* d_out, int out_size) {
    const float* x  = (const float*)d_in[0];
    const float* cb = (const float*)d_in[1];
    float* out      = (float*)d_out;
    float* out_disc = out;
    float* out_q    = out + (size_t)N_ROWS * N_CODES;

    const int smem = BM * ROWB + 2 * BBUF;   // 76800
    cudaFuncSetAttribute(argmin_fused, cudaFuncAttributeMaxDynamicSharedMemorySize, smem);

    prep_kernel<<<(N_CODES * 32) / 256, 256>>>(cb);
    argmin_fused<<<NARG + NZERO, THREADS, smem>>>(x, out_disc);
    finalize_kernel<<<(N_ROWS * (DIM / 4)) / 256, 256>>>(cb, out_disc, out_q);
}

// round 7
// speedup vs baseline: 2.4780x; 1.0729x over previous
#include <cuda_runtime.h>
#include <cuda_fp16.h>
#include <cstdint>

#define N_ROWS   16384
#define N_CODES  8192
#define DIM      64
#define BM       128
#define BN       32
#define NCHUNK   (N_CODES / BN)      // 256
#define THREADS  256
#define ROWB     272                  // padded row bytes (17*16; 17 mod 8 = 1 -> conflict-free LDSM)
#define BBUF     (BN * ROWB)          // 8704 B per B stage
#define NARG     (N_ROWS / BM)        // 128 argmin CTAs
#define NZERO    128                  // zerofill CTAs
#define DISC_F4  ((size_t)N_ROWS * N_CODES / 4)

// device scratch: [ch(128B) | cl(128B)] per code
__device__ __align__(16) __half g_cbe[(size_t)N_CODES * 128];
__device__ __align__(16) float  g_cnorm[N_CODES];
__device__ int g_idx[N_ROWS];

// ---------------- helpers ----------------
__device__ __forceinline__ uint32_t h2_as_u32(__half2 h) {
    uint32_t u;
    __builtin_memcpy(&u, &h, 4);
    return u;
}
__device__ __forceinline__ uint32_t pack_h2(__half a, __half b) {
    return h2_as_u32(__halves2half2(a, b));
}
__device__ __forceinline__ uint32_t smem_u32(const void* p) {
    uint32_t a;
    asm("{ .reg .u64 t; cvta.to.shared.u64 t, %1; cvt.u32.u64 %0, t; }" : "=r"(a) : "l"(p));
    return a;
}
#define CPA16(d,s)   asm volatile("cp.async.cg.shared.global [%0], [%1], 16;" :: "r"(d), "l"(s) : "memory")
#define CPA_COMMIT() asm volatile("cp.async.commit_group;" ::: "memory")
#define CPA_WAIT0()  asm volatile("cp.async.wait_group 0;" ::: "memory")

#define LDM_X4(r0,r1,r2,r3,a) \
    asm volatile("ldmatrix.sync.aligned.m8n8.x4.shared.b16 {%0,%1,%2,%3}, [%4];" \
                 : "=r"(r0), "=r"(r1), "=r"(r2), "=r"(r3) : "r"(a))

__device__ __forceinline__ void mma16816(float* d, const uint32_t* a,
                                         uint32_t b0, uint32_t b1) {
    asm volatile("mma.sync.aligned.m16n8k16.row.col.f32.f16.f16.f32 "
                 "{%0,%1,%2,%3}, {%4,%5,%6,%7}, {%8,%9}, {%0,%1,%2,%3};"
                 : "+f"(d[0]), "+f"(d[1]), "+f"(d[2]), "+f"(d[3])
                 : "r"(a[0]), "r"(a[1]), "r"(a[2]), "r"(a[3]), "r"(b0), "r"(b1));
}

// ---------------------------------------------------------------------------
// Prep: codebook -> fp16 [ch|cl] + squared norms. One warp per code.
// ---------------------------------------------------------------------------
__global__ void prep_kernel(const float* __restrict__ cb) {
    int g = blockIdx.x * blockDim.x + threadIdx.x;
    int code = g >> 5, lane = g & 31;
    float2 v = reinterpret_cast<const float2*>(cb + (size_t)code * DIM)[lane];
    __half hx = __float2half_rn(v.x), hy = __float2half_rn(v.y);
    float lx = v.x - __half2float(hx), ly = v.y - __half2float(hy);
    __half2* dst = reinterpret_cast<__half2*>(g_cbe + (size_t)code * 128);
    dst[lane]      = __halves2half2(hx, hy);                                   // ch
    dst[32 + lane] = __halves2half2(__float2half_rn(lx), __float2half_rn(ly)); // cl
    float s = v.x * v.x + v.y * v.y;
#pragma unroll
    for (int o = 16; o; o >>= 1) s += __shfl_xor_sync(~0u, s, o);
    if (lane == 0) g_cnorm[code] = s;
}

// ---------------------------------------------------------------------------
// Fused: bid < NARG -> mma.sync distance GEMM + argmin;
//        bid >= NARG -> stream zeros into the one-hot output concurrently.
// dot = xh.ch + xl.ch + xh.cl via fragment reuse (B streamed once).
// ---------------------------------------------------------------------------
__global__ void __launch_bounds__(THREADS, 1)
argmin_fused(const float* __restrict__ x, float* __restrict__ out_disc) {
    const int tid = threadIdx.x;

    if (blockIdx.x >= NARG) {
        size_t i = (size_t)(blockIdx.x - NARG) * THREADS + tid;
        const size_t stride = (size_t)NZERO * THREADS;
        float4 z = make_float4(0.f, 0.f, 0.f, 0.f);
        float4* o = reinterpret_cast<float4*>(out_disc);
#pragma unroll 4
        for (; i < DISC_F4; i += stride) __stcs(o + i, z);
        return;
    }

    extern __shared__ char smem[];
    const uint32_t As = smem_u32(smem);            // [128][272] : [xh|xl]
    const uint32_t Bs = As + BM * ROWB;            // B ring [2][8704]

    const int wid = tid >> 5, lane = tid & 31;
    const int row0 = blockIdx.x * BM;

    // ---- Build A staging: row = [xh(128B) | xl(128B)] ----
    for (int t = tid; t < BM * (DIM / 4); t += THREADS) {
        int row = t >> 4, q = t & 15;
        float4 v = reinterpret_cast<const float4*>(x)[(size_t)(row0 + row) * 16 + q];
        __half h0 = __float2half_rn(v.x), h1 = __float2half_rn(v.y);
        __half h2 = __float2half_rn(v.z), h3 = __float2half_rn(v.w);
        uint32_t hp0 = pack_h2(h0, h1);
        uint32_t hp1 = pack_h2(h2, h3);
        uint32_t lp0 = pack_h2(__float2half_rn(v.x - __half2float(h0)),
                               __float2half_rn(v.y - __half2float(h1)));
        uint32_t lp1 = pack_h2(__float2half_rn(v.z - __half2float(h2)),
                               __float2half_rn(v.w - __half2float(h3)));
        uint32_t base = As + row * ROWB + q * 8;
        asm volatile("st.shared.v2.b32 [%0], {%1,%2};" :: "r"(base), "r"(hp0), "r"(hp1));
        asm volatile("st.shared.v2.b32 [%0], {%1,%2};" :: "r"(base + 128), "r"(lp0), "r"(lp1));
    }
    __syncthreads();

    // ---- Persistent A fragments: 8 kgroups (0-3 = xh, 4-7 = xl) ----
    uint32_t afr[8][4];
    {
        int t = lane >> 3;
        int arow = wid * 16 + ((t & 1) << 3) + (lane & 7);
        uint32_t abase = As + arow * ROWB + ((t >> 1) << 4);
#pragma unroll
        for (int kg = 0; kg < 8; kg++)
            LDM_X4(afr[kg][0], afr[kg][1], afr[kg][2], afr[kg][3], abase + kg * 32);
    }
    __syncthreads();

    const uint32_t bl0 = Bs + ((lane >> 4) * 8 + (lane & 7)) * ROWB + ((lane >> 3) & 1) * 16;

    // ---- prefetch chunk 0 (32 codes x 256B = 512 x 16B ops) ----
    {
#pragma unroll
        for (int j = 0; j < 2; j++) {
            int i = tid + j * THREADS;
            int code = i >> 4, off = (i & 15) * 16;
            CPA16(Bs + code * ROWB + off, (const char*)g_cbe + i * 16);
        }
        CPA_COMMIT();
    }

    float best0 = 3.4e38f, best1 = 3.4e38f;
    int idx0 = 0, idx1 = 0;

    for (int c = 0; c < NCHUNK; c++) {
        CPA_WAIT0();
        __syncthreads();
        if (c + 1 < NCHUNK) {
            const char* src = (const char*)g_cbe + (size_t)(c + 1) * BN * 256;
            uint32_t dbuf = Bs + ((c + 1) & 1) * BBUF;
#pragma unroll
            for (int j = 0; j < 2; j++) {
                int i = tid + j * THREADS;
                int code = i >> 4, off = (i & 15) * 16;
                CPA16(dbuf + code * ROWB + off, src + i * 16);
            }
            CPA_COMMIT();
        }

        const uint32_t bb = bl0 + (c & 1) * BBUF;
        float acc[4][4];
#pragma unroll
        for (int f = 0; f < 4; f++)
#pragma unroll
            for (int j = 0; j < 4; j++) acc[f][j] = 0.f;

        uint32_t b[4][8];
        // load ch fragments once
#pragma unroll
        for (int t = 0; t < 4; t++) {
            LDM_X4(b[t][0], b[t][1], b[t][2], b[t][3], bb + t * 32);
            LDM_X4(b[t][4], b[t][5], b[t][6], b[t][7], bb + t * 32 + 16 * ROWB);
        }
        // pass 1: xh . ch
#pragma unroll
        for (int t = 0; t < 4; t++) {
            mma16816(acc[0], afr[t], b[t][0], b[t][1]);
            mma16816(acc[1], afr[t], b[t][2], b[t][3]);
            mma16816(acc[2], afr[t], b[t][4], b[t][5]);
            mma16816(acc[3], afr[t], b[t][6], b[t][7]);
        }
        // pass 2: xl . ch (reuse ch fragments)
#pragma unroll
        for (int t = 0; t < 4; t++) {
            mma16816(acc[0], afr[4 + t], b[t][0], b[t][1]);
            mma16816(acc[1], afr[4 + t], b[t][2], b[t][3]);
            mma16816(acc[2], afr[4 + t], b[t][4], b[t][5]);
            mma16816(acc[3], afr[4 + t], b[t][6], b[t][7]);
        }
        // load cl fragments, pass 3: xh . cl
#pragma unroll
        for (int t = 0; t < 4; t++) {
            LDM_X4(b[t][0], b[t][1], b[t][2], b[t][3], bb + 128 + t * 32);
            LDM_X4(b[t][4], b[t][5], b[t][6], b[t][7], bb + 128 + t * 32 + 16 * ROWB);
        }
#pragma unroll
        for (int t = 0; t < 4; t++) {
            mma16816(acc[0], afr[t], b[t][0], b[t][1]);
            mma16816(acc[1], afr[t], b[t][2], b[t][3]);
            mma16816(acc[2], afr[t], b[t][4], b[t][5]);
            mma16816(acc[3], afr[t], b[t][6], b[t][7]);
        }

        int base = c * BN + ((lane & 3) << 1);
#pragma unroll
        for (int f = 0; f < 4; f++) {
            int col = base + f * 8;
            float cn0 = __ldg(&g_cnorm[col]);
            float cn1 = __ldg(&g_cnorm[col + 1]);
            float d0 = fmaf(-2.f, acc[f][0], cn0);
            float d1 = fmaf(-2.f, acc[f][1], cn1);
            float d2 = fmaf(-2.f, acc[f][2], cn0);
            float d3 = fmaf(-2.f, acc[f][3], cn1);
            if (d0 < best0) { best0 = d0; idx0 = col; }
            if (d1 < best0) { best0 = d1; idx0 = col + 1; }
            if (d2 < best1) { best1 = d2; idx1 = col; }
            if (d3 < best1) { best1 = d3; idx1 = col + 1; }
        }
    }

#pragma unroll
    for (int off = 1; off <= 2; off <<= 1) {
        float ob = __shfl_xor_sync(~0u, best0, off);
        int   oi = __shfl_xor_sync(~0u, idx0, off);
        if (ob < best0 || (ob == best0 && oi < idx0)) { best0 = ob; idx0 = oi; }
        ob = __shfl_xor_sync(~0u, best1, off);
        oi = __shfl_xor_sync(~0u, idx1, off);
        if (ob < best1 || (ob == best1 && oi < idx1)) { best1 = ob; idx1 = oi; }
    }
    if ((lane & 3) == 0) {
        int r = row0 + wid * 16 + (lane >> 2);
        g_idx[r] = idx0;
        g_idx[r + 8] = idx1;
    }
}

// ---------------------------------------------------------------------------
// Finalize: gather quantized rows + scatter the 1.0s into the one-hot.
// ---------------------------------------------------------------------------
__global__ void finalize_kernel(const float* __restrict__ cb,
                                float* __restrict__ out_disc,
                                float* __restrict__ outq) {
    unsigned i = blockIdx.x * 256u + threadIdx.x;
    unsigned n = i >> 4;
    unsigned c4 = i & 15u;
    int k = __ldg(&g_idx[n]);
    reinterpret_cast<float4*>(outq)[i] =
        reinterpret_cast<const float4*>(cb + (size_t)k * DIM)[c4];
    if (c4 == 0) out_disc[(size_t)n * N_CODES + k] = 1.0f;
}

// ---------------------------------------------------------------------------
extern "C" void kernel_launch(void* const* d_in, const int* in_sizes, int n_in,
                              void* d_out, int out_size) {
    const float* x  = (const float*)d_in[0];
    const float* cb = (const float*)d_in[1];
    float* out      = (float*)d_out;
    float* out_disc = out;
    float* out_q    = out + (size_t)N_ROWS * N_CODES;

    const int smem = BM * ROWB + 2 * BBUF;   // 34816 + 17408 = 52224
    cudaFuncSetAttribute(argmin_fused, cudaFuncAttributeMaxDynamicSharedMemorySize, smem);

    prep_kernel<<<(N_CODES * 32) / 256, 256>>>(cb);
    argmin_fused<<<NARG + NZERO, THREADS, smem>>>(x, out_disc);
    finalize_kernel<<<(N_ROWS * (DIM / 4)) / 256, 256>>>(cb, out_disc, out_q);
}